// round 1
// baseline (speedup 1.0000x reference)
#include <cuda_runtime.h>
#include <cstdint>

// Problem constants (fixed by the reference)
#define K_DIM       2048
#define N_DIM       1024
#define ROWS_WHOLE  8192      // 4 * 2048
#define ROWS_PARTS  32768     // 4 * 4 * 2048
#define ROWS_TOTAL  40960

#define BM 64
#define BN 64
#define BK 16
#define AS_STRIDE 68   // floats, padded (272B, 16B-aligned rows)
#define BS_STRIDE 65   // u64 elements, padded

typedef unsigned long long u64;

// Per-row sum-of-squares scratch (no allocations allowed — device global)
__device__ float g_sumsq[ROWS_TOTAL];

__device__ __forceinline__ u64 ffma2(u64 a, u64 b, u64 c) {
    u64 d;
    asm("fma.rn.f32x2 %0, %1, %2, %3;" : "=l"(d) : "l"(a), "l"(b), "l"(c));
    return d;
}
__device__ __forceinline__ u64 pack2(float lo, float hi) {
    u64 v;
    asm("mov.b64 %0, {%1, %2};" : "=l"(v) : "f"(lo), "f"(hi));
    return v;
}
__device__ __forceinline__ void unpack2(u64 v, float& lo, float& hi) {
    asm("mov.b64 {%0, %1}, %2;" : "=f"(lo), "=f"(hi) : "l"(v));
}

__global__ void zero_kernel() {
    int i = blockIdx.x * 256 + threadIdx.x;
    if (i < ROWS_TOTAL) g_sumsq[i] = 0.0f;
}

// C = A[M,2048] * W^T[2048,1024]; accumulate per-row sum((c + bias[n])^2)
// into g_sumsq[row_off + m] via atomics. Never materializes C.
__global__ __launch_bounds__(256, 3)
void gemm_sumsq_kernel(const float* __restrict__ A,
                       const float* __restrict__ W,
                       const float* __restrict__ bias,
                       int row_off)
{
    __shared__ __align__(16) float As[BK * AS_STRIDE];
    __shared__ __align__(16) u64   Bs[BK * BS_STRIDE];

    const int tid = threadIdx.x;
    const int tx  = tid & 15;        // 0..15 -> column groups
    const int ty  = tid >> 4;        // 0..15 -> row groups (4 rows each)
    const int m0  = blockIdx.y * BM;
    const int n0  = blockIdx.x * BN;

    const int lr = tid >> 2;          // 0..63 : tile row loaded by this thread
    const int lk = (tid & 3) << 2;    // 0,4,8,12 : k offset within tile

    const float4* Aload = (const float4*)(A + (size_t)(m0 + lr) * K_DIM + lk);
    const float4* Wload = (const float4*)(W + (size_t)(n0 + lr) * K_DIM + lk);

    u64 acc[4][2];
#pragma unroll
    for (int j = 0; j < 4; j++) { acc[j][0] = 0ull; acc[j][1] = 0ull; }

    float4 ra = Aload[0];
    float4 rb = Wload[0];

    const int KT = K_DIM / BK;   // 128
    for (int kt = 0; kt < KT; kt++) {
        __syncthreads();
        As[(lk + 0) * AS_STRIDE + lr] = ra.x;
        As[(lk + 1) * AS_STRIDE + lr] = ra.y;
        As[(lk + 2) * AS_STRIDE + lr] = ra.z;
        As[(lk + 3) * AS_STRIDE + lr] = ra.w;
        Bs[(lk + 0) * BS_STRIDE + lr] = pack2(rb.x, rb.x);
        Bs[(lk + 1) * BS_STRIDE + lr] = pack2(rb.y, rb.y);
        Bs[(lk + 2) * BS_STRIDE + lr] = pack2(rb.z, rb.z);
        Bs[(lk + 3) * BS_STRIDE + lr] = pack2(rb.w, rb.w);
        __syncthreads();

        if (kt + 1 < KT) {           // prefetch next tile into registers
            ra = Aload[(kt + 1) * (BK / 4)];
            rb = Wload[(kt + 1) * (BK / 4)];
        }

#pragma unroll
        for (int kk = 0; kk < BK; kk++) {
            // 4 consecutive rows for this thread, as two f32x2 pairs
            ulonglong2 a2 = *(const ulonglong2*)&As[kk * AS_STRIDE + (ty << 2)];
#pragma unroll
            for (int j = 0; j < 4; j++) {
                // broadcast pair (b,b); columns strided: n = n0 + tx + 16*j
                u64 bj = Bs[kk * BS_STRIDE + tx + (j << 4)];
                acc[j][0] = ffma2(a2.x, bj, acc[j][0]);   // rows 4ty+0,1
                acc[j][1] = ffma2(a2.y, bj, acc[j][1]);   // rows 4ty+2,3
            }
        }
    }

    // Epilogue: add bias, square, reduce over this thread's 4 columns
    float rowsq[4] = {0.f, 0.f, 0.f, 0.f};
#pragma unroll
    for (int j = 0; j < 4; j++) {
        float bn = bias[n0 + tx + (j << 4)];
        float c0, c1, c2, c3;
        unpack2(acc[j][0], c0, c1);
        unpack2(acc[j][1], c2, c3);
        c0 += bn; c1 += bn; c2 += bn; c3 += bn;
        rowsq[0] += c0 * c0;
        rowsq[1] += c1 * c1;
        rowsq[2] += c2 * c2;
        rowsq[3] += c3 * c3;
    }

    // Reduce across the 16 tx lanes sharing the same 4 rows (width-16 segments)
#pragma unroll
    for (int off = 8; off > 0; off >>= 1) {
        rowsq[0] += __shfl_down_sync(0xffffffffu, rowsq[0], off, 16);
        rowsq[1] += __shfl_down_sync(0xffffffffu, rowsq[1], off, 16);
        rowsq[2] += __shfl_down_sync(0xffffffffu, rowsq[2], off, 16);
        rowsq[3] += __shfl_down_sync(0xffffffffu, rowsq[3], off, 16);
    }
    if (tx == 0) {
        int mrow = row_off + m0 + (ty << 2);
        atomicAdd(&g_sumsq[mrow + 0], rowsq[0]);
        atomicAdd(&g_sumsq[mrow + 1], rowsq[1]);
        atomicAdd(&g_sumsq[mrow + 2], rowsq[2]);
        atomicAdd(&g_sumsq[mrow + 3], rowsq[3]);
    }
}

// out[b] = clip(scale*(w-p)/(w+eps)+bias, 0, 1)
__global__ void finalize_kernel(const float* __restrict__ phi_scale,
                                const float* __restrict__ phi_bias,
                                float* __restrict__ out)
{
    const int b = blockIdx.x;
    const int tid = threadIdx.x;

    float lw = 0.f, lp = 0.f;
    for (int i = tid; i < 2048; i += 256)
        lw += sqrtf(g_sumsq[b * 2048 + i]);
#pragma unroll
    for (int h = 0; h < 4; h++) {
        int base = ROWS_WHOLE + h * ROWS_WHOLE + b * 2048;
        for (int i = tid; i < 2048; i += 256)
            lp += sqrtf(g_sumsq[base + i]);
    }

    __shared__ float sw[256];
    __shared__ float sp[256];
    sw[tid] = lw; sp[tid] = lp;
    __syncthreads();
    for (int s = 128; s > 0; s >>= 1) {
        if (tid < s) { sw[tid] += sw[tid + s]; sp[tid] += sp[tid + s]; }
        __syncthreads();
    }
    if (tid == 0) {
        float w = sw[0] / 2048.0f;
        float p = sp[0] / 8192.0f;
        float raw = (w - p) / (w + 1e-8f);
        float phi = phi_scale[0] * raw + phi_bias[0];
        out[b] = fminf(fmaxf(phi, 0.0f), 1.0f);
    }
}

extern "C" void kernel_launch(void* const* d_in, const int* in_sizes, int n_in,
                              void* d_out, int out_size)
{
    const float* cur  = (const float*)d_in[0];   // [4,2048,2048]
    const float* hist = (const float*)d_in[1];   // [4,4,2048,2048]
    const float* Ww   = (const float*)d_in[2];   // [1024,2048]
    const float* bw   = (const float*)d_in[3];   // [1024]
    const float* Wp   = (const float*)d_in[4];   // [1024,2048]
    const float* bp   = (const float*)d_in[5];   // [1024]
    const float* ps   = (const float*)d_in[6];   // scalar
    const float* pb   = (const float*)d_in[7];   // scalar
    float* out = (float*)d_out;                  // [4]

    zero_kernel<<<(ROWS_TOTAL + 255) / 256, 256>>>();

    gemm_sumsq_kernel<<<dim3(N_DIM / BN, ROWS_WHOLE / BM), 256>>>(cur, Ww, bw, 0);
    gemm_sumsq_kernel<<<dim3(N_DIM / BN, ROWS_PARTS / BM), 256>>>(hist, Wp, bp, ROWS_WHOLE);

    finalize_kernel<<<4, 256>>>(ps, pb, out);
}

// round 2
// speedup vs baseline: 1.0004x; 1.0004x over previous
#include <cuda_runtime.h>
#include <cstdint>

// Problem constants (fixed by the reference)
#define K_DIM       2048
#define N_DIM       1024
#define ROWS_WHOLE  8192      // 4 * 2048
#define ROWS_PARTS  32768     // 4 * 4 * 2048
#define ROWS_TOTAL  40960

#define BM 64
#define BN 64
#define BK 16
#define AS_STRIDE 68   // floats, padded (272B, 16B-aligned rows)
#define BS_STRIDE 65   // u64 elements, padded

typedef unsigned long long u64;

// Per-row sum-of-squares scratch (no allocations allowed — device global)
__device__ float g_sumsq[ROWS_TOTAL];

__device__ __forceinline__ u64 ffma2(u64 a, u64 b, u64 c) {
    u64 d;
    asm("fma.rn.f32x2 %0, %1, %2, %3;" : "=l"(d) : "l"(a), "l"(b), "l"(c));
    return d;
}
__device__ __forceinline__ u64 pack2(float lo, float hi) {
    u64 v;
    asm("mov.b64 %0, {%1, %2};" : "=l"(v) : "f"(lo), "f"(hi));
    return v;
}
__device__ __forceinline__ void unpack2(u64 v, float& lo, float& hi) {
    asm("mov.b64 {%0, %1}, %2;" : "=f"(lo), "=f"(hi) : "l"(v));
}

__global__ void zero_kernel() {
    int i = blockIdx.x * 256 + threadIdx.x;
    if (i < ROWS_TOTAL) g_sumsq[i] = 0.0f;
}

// C = A[M,2048] * W^T[2048,1024]; accumulate per-row sum((c + bias[n])^2)
// into g_sumsq[row_off + m] via atomics. Never materializes C.
__global__ __launch_bounds__(256, 3)
void gemm_sumsq_kernel(const float* __restrict__ A,
                       const float* __restrict__ W,
                       const float* __restrict__ bias,
                       int row_off)
{
    __shared__ __align__(16) float As[BK * AS_STRIDE];
    __shared__ __align__(16) u64   Bs[BK * BS_STRIDE];

    const int tid = threadIdx.x;
    const int tx  = tid & 15;        // 0..15 -> column groups
    const int ty  = tid >> 4;        // 0..15 -> row groups (4 rows each)
    const int m0  = blockIdx.y * BM;
    const int n0  = blockIdx.x * BN;

    const int lr = tid >> 2;          // 0..63 : tile row loaded by this thread
    const int lk = (tid & 3) << 2;    // 0,4,8,12 : k offset within tile

    const float4* Aload = (const float4*)(A + (size_t)(m0 + lr) * K_DIM + lk);
    const float4* Wload = (const float4*)(W + (size_t)(n0 + lr) * K_DIM + lk);

    u64 acc[4][2];
#pragma unroll
    for (int j = 0; j < 4; j++) { acc[j][0] = 0ull; acc[j][1] = 0ull; }

    float4 ra = Aload[0];
    float4 rb = Wload[0];

    const int KT = K_DIM / BK;   // 128
    for (int kt = 0; kt < KT; kt++) {
        __syncthreads();
        As[(lk + 0) * AS_STRIDE + lr] = ra.x;
        As[(lk + 1) * AS_STRIDE + lr] = ra.y;
        As[(lk + 2) * AS_STRIDE + lr] = ra.z;
        As[(lk + 3) * AS_STRIDE + lr] = ra.w;
        Bs[(lk + 0) * BS_STRIDE + lr] = pack2(rb.x, rb.x);
        Bs[(lk + 1) * BS_STRIDE + lr] = pack2(rb.y, rb.y);
        Bs[(lk + 2) * BS_STRIDE + lr] = pack2(rb.z, rb.z);
        Bs[(lk + 3) * BS_STRIDE + lr] = pack2(rb.w, rb.w);
        __syncthreads();

        if (kt + 1 < KT) {           // prefetch next tile into registers
            ra = Aload[(kt + 1) * (BK / 4)];
            rb = Wload[(kt + 1) * (BK / 4)];
        }

#pragma unroll
        for (int kk = 0; kk < BK; kk++) {
            // 4 consecutive rows for this thread, as two f32x2 pairs
            ulonglong2 a2 = *(const ulonglong2*)&As[kk * AS_STRIDE + (ty << 2)];
#pragma unroll
            for (int j = 0; j < 4; j++) {
                // broadcast pair (b,b); columns strided: n = n0 + tx + 16*j
                u64 bj = Bs[kk * BS_STRIDE + tx + (j << 4)];
                acc[j][0] = ffma2(a2.x, bj, acc[j][0]);   // rows 4ty+0,1
                acc[j][1] = ffma2(a2.y, bj, acc[j][1]);   // rows 4ty+2,3
            }
        }
    }

    // Epilogue: add bias, square, reduce over this thread's 4 columns
    float rowsq[4] = {0.f, 0.f, 0.f, 0.f};
#pragma unroll
    for (int j = 0; j < 4; j++) {
        float bn = bias[n0 + tx + (j << 4)];
        float c0, c1, c2, c3;
        unpack2(acc[j][0], c0, c1);
        unpack2(acc[j][1], c2, c3);
        c0 += bn; c1 += bn; c2 += bn; c3 += bn;
        rowsq[0] += c0 * c0;
        rowsq[1] += c1 * c1;
        rowsq[2] += c2 * c2;
        rowsq[3] += c3 * c3;
    }

    // Reduce across the 16 tx lanes sharing the same 4 rows (width-16 segments)
#pragma unroll
    for (int off = 8; off > 0; off >>= 1) {
        rowsq[0] += __shfl_down_sync(0xffffffffu, rowsq[0], off, 16);
        rowsq[1] += __shfl_down_sync(0xffffffffu, rowsq[1], off, 16);
        rowsq[2] += __shfl_down_sync(0xffffffffu, rowsq[2], off, 16);
        rowsq[3] += __shfl_down_sync(0xffffffffu, rowsq[3], off, 16);
    }
    if (tx == 0) {
        int mrow = row_off + m0 + (ty << 2);
        atomicAdd(&g_sumsq[mrow + 0], rowsq[0]);
        atomicAdd(&g_sumsq[mrow + 1], rowsq[1]);
        atomicAdd(&g_sumsq[mrow + 2], rowsq[2]);
        atomicAdd(&g_sumsq[mrow + 3], rowsq[3]);
    }
}

// out[b] = clip(scale*(w-p)/(w+eps)+bias, 0, 1)
__global__ void finalize_kernel(const float* __restrict__ phi_scale,
                                const float* __restrict__ phi_bias,
                                float* __restrict__ out)
{
    const int b = blockIdx.x;
    const int tid = threadIdx.x;

    float lw = 0.f, lp = 0.f;
    for (int i = tid; i < 2048; i += 256)
        lw += sqrtf(g_sumsq[b * 2048 + i]);
#pragma unroll
    for (int h = 0; h < 4; h++) {
        int base = ROWS_WHOLE + h * ROWS_WHOLE + b * 2048;
        for (int i = tid; i < 2048; i += 256)
            lp += sqrtf(g_sumsq[base + i]);
    }

    __shared__ float sw[256];
    __shared__ float sp[256];
    sw[tid] = lw; sp[tid] = lp;
    __syncthreads();
    for (int s = 128; s > 0; s >>= 1) {
        if (tid < s) { sw[tid] += sw[tid + s]; sp[tid] += sp[tid + s]; }
        __syncthreads();
    }
    if (tid == 0) {
        float w = sw[0] / 2048.0f;
        float p = sp[0] / 8192.0f;
        float raw = (w - p) / (w + 1e-8f);
        float phi = phi_scale[0] * raw + phi_bias[0];
        out[b] = fminf(fmaxf(phi, 0.0f), 1.0f);
    }
}

extern "C" void kernel_launch(void* const* d_in, const int* in_sizes, int n_in,
                              void* d_out, int out_size)
{
    const float* cur  = (const float*)d_in[0];   // [4,2048,2048]
    const float* hist = (const float*)d_in[1];   // [4,4,2048,2048]
    const float* Ww   = (const float*)d_in[2];   // [1024,2048]
    const float* bw   = (const float*)d_in[3];   // [1024]
    const float* Wp   = (const float*)d_in[4];   // [1024,2048]
    const float* bp   = (const float*)d_in[5];   // [1024]
    const float* ps   = (const float*)d_in[6];   // scalar
    const float* pb   = (const float*)d_in[7];   // scalar
    float* out = (float*)d_out;                  // [4]

    zero_kernel<<<(ROWS_TOTAL + 255) / 256, 256>>>();

    gemm_sumsq_kernel<<<dim3(N_DIM / BN, ROWS_WHOLE / BM), 256>>>(cur, Ww, bw, 0);
    gemm_sumsq_kernel<<<dim3(N_DIM / BN, ROWS_PARTS / BM), 256>>>(hist, Wp, bp, ROWS_WHOLE);

    finalize_kernel<<<4, 256>>>(ps, pb, out);
}

// round 4
// speedup vs baseline: 1.9980x; 1.9973x over previous
#include <cuda_runtime.h>
#include <cstdint>

// ---------------- problem constants ----------------
#define K_DIM       2048
#define N_DIM       1024
#define ROWS_WHOLE  8192
#define ROWS_PARTS  32768
#define ROWS_TOTAL  40960

// ---------------- tile config ----------------
#define BM 128
#define BN 128
#define BK 16                      // fp32 elements per K chunk
#define NCHUNK (K_DIM / BK)        // 128
#define SA 20                      // smem row stride in floats (16 + 4 pad)

// SMEM stage layout (floats): Ahi[128*20] Alo Bhi Blo
#define A_F      (BM * SA)         // 2560 floats
#define AHI_F    0
#define ALO_F    (A_F)
#define BHI_F    (2 * A_F)
#define BLO_F    (3 * A_F)
#define STAGE_F  (4 * A_F)         // 10240 floats = 40960 B
#define BIAS_F   (2 * STAGE_F)     // after both stages
#define SMEM_FLOATS (BIAS_F + BN)
#define SMEM_BYTES  (SMEM_FLOATS * 4)   // 82432

__device__ float g_sumsq[ROWS_TOTAL];

// ---------------- helpers ----------------
__device__ __forceinline__ uint32_t cvt_tf32(float x) {
    uint32_t r;
    asm("cvt.rna.tf32.f32 %0, %1;" : "=r"(r) : "f"(x));
    return r;
}

__device__ __forceinline__ void split4(float4 v, float4& h, float4& l) {
    h.x = __uint_as_float(cvt_tf32(v.x));
    h.y = __uint_as_float(cvt_tf32(v.y));
    h.z = __uint_as_float(cvt_tf32(v.z));
    h.w = __uint_as_float(cvt_tf32(v.w));
    l.x = __uint_as_float(cvt_tf32(v.x - h.x));
    l.y = __uint_as_float(cvt_tf32(v.y - h.y));
    l.z = __uint_as_float(cvt_tf32(v.z - h.z));
    l.w = __uint_as_float(cvt_tf32(v.w - h.w));
}

__device__ __forceinline__ void mma8(float* c,
                                     uint32_t a0, uint32_t a1, uint32_t a2, uint32_t a3,
                                     uint32_t b0, uint32_t b1) {
    asm volatile(
        "mma.sync.aligned.m16n8k8.row.col.f32.tf32.tf32.f32 "
        "{%0,%1,%2,%3}, {%4,%5,%6,%7}, {%8,%9}, {%0,%1,%2,%3};"
        : "+f"(c[0]), "+f"(c[1]), "+f"(c[2]), "+f"(c[3])
        : "r"(a0), "r"(a1), "r"(a2), "r"(a3), "r"(b0), "r"(b1));
}

__global__ void zero_kernel() {
    int i = blockIdx.x * 256 + threadIdx.x;
    if (i < ROWS_TOTAL) g_sumsq[i] = 0.0f;
}

// ---------------- fused 3xTF32 mma.sync GEMM + row sum-of-squares ----------------
__global__ __launch_bounds__(256, 1)
void gemm3xtf32_kernel(const float* __restrict__ A,
                       const float* __restrict__ W,
                       const float* __restrict__ bias,
                       int row_off)
{
    extern __shared__ __align__(16) float smem[];
    const int tid = threadIdx.x;
    const int wid = tid >> 5;
    const int lid = tid & 31;
    const int wm  = wid >> 2;          // 0..1 : warp row (64 rows)
    const int wn  = wid & 3;           // 0..3 : warp col (32 cols)
    const int r   = lid >> 2;          // 0..7
    const int cq  = lid & 3;           // 0..3
    const int m0  = blockIdx.y * BM;
    const int n0  = blockIdx.x * BN;

    float* sbias = smem + BIAS_F;
    if (tid < BN) sbias[tid] = bias[n0 + tid];

    // global load coords: each thread loads 2 float4 of A and 2 of W per chunk
    const int ar = tid >> 1;           // 0..127
    const int ac = (tid & 1) << 3;     // 0 or 8
    const float* Aptr = A + (size_t)(m0 + ar) * K_DIM + ac;
    const float* Wptr = W + (size_t)(n0 + ar) * K_DIM + ac;
    const int s_off = ar * SA + ac;    // smem store offset (floats)

    float acc[4][4][4];
#pragma unroll
    for (int i = 0; i < 4; i++)
#pragma unroll
        for (int j = 0; j < 4; j++)
#pragma unroll
            for (int q = 0; q < 4; q++) acc[i][j][q] = 0.f;

    float4 av0, av1, bv0, bv1;

#define LOADCHUNK(kc) do { \
        const float* ap_ = Aptr + (size_t)(kc) * BK; \
        av0 = *(const float4*)ap_;  av1 = *(const float4*)(ap_ + 4); \
        const float* wp_ = Wptr + (size_t)(kc) * BK; \
        bv0 = *(const float4*)wp_;  bv1 = *(const float4*)(wp_ + 4); \
    } while (0)

#define STORESTAGE(s) do { \
        float* st_ = smem + (s) * STAGE_F; \
        float4 h_, l_; \
        split4(av0, h_, l_); \
        *(float4*)(st_ + AHI_F + s_off)     = h_; *(float4*)(st_ + ALO_F + s_off)     = l_; \
        split4(av1, h_, l_); \
        *(float4*)(st_ + AHI_F + s_off + 4) = h_; *(float4*)(st_ + ALO_F + s_off + 4) = l_; \
        split4(bv0, h_, l_); \
        *(float4*)(st_ + BHI_F + s_off)     = h_; *(float4*)(st_ + BLO_F + s_off)     = l_; \
        split4(bv1, h_, l_); \
        *(float4*)(st_ + BHI_F + s_off + 4) = h_; *(float4*)(st_ + BLO_F + s_off + 4) = l_; \
    } while (0)

    LOADCHUNK(0);
    STORESTAGE(0);
    LOADCHUNK(1);
    __syncthreads();

    for (int kc = 0; kc < NCHUNK; kc++) {
        const float* st = smem + (kc & 1) * STAGE_F;
        const float* Ah = st + AHI_F;
        const float* Al = st + ALO_F;
        const float* Bh = st + BHI_F;
        const float* Bl = st + BLO_F;

#pragma unroll
        for (int ks = 0; ks < 2; ks++) {
            const int k0 = ks * 8 + cq;
            uint32_t ah[4][4], al[4][4], bh[4][2], bl[4][2];
#pragma unroll
            for (int mf = 0; mf < 4; mf++) {
                const int base = (wm * 64 + mf * 16 + r) * SA + k0;
                ah[mf][0] = __float_as_uint(Ah[base]);
                ah[mf][1] = __float_as_uint(Ah[base + 8 * SA]);
                ah[mf][2] = __float_as_uint(Ah[base + 4]);
                ah[mf][3] = __float_as_uint(Ah[base + 8 * SA + 4]);
                al[mf][0] = __float_as_uint(Al[base]);
                al[mf][1] = __float_as_uint(Al[base + 8 * SA]);
                al[mf][2] = __float_as_uint(Al[base + 4]);
                al[mf][3] = __float_as_uint(Al[base + 8 * SA + 4]);
            }
#pragma unroll
            for (int nf = 0; nf < 4; nf++) {
                const int base = (wn * 32 + nf * 8 + r) * SA + k0;
                bh[nf][0] = __float_as_uint(Bh[base]);
                bh[nf][1] = __float_as_uint(Bh[base + 4]);
                bl[nf][0] = __float_as_uint(Bl[base]);
                bl[nf][1] = __float_as_uint(Bl[base + 4]);
            }
#pragma unroll
            for (int mf = 0; mf < 4; mf++)
#pragma unroll
                for (int nf = 0; nf < 4; nf++) {
                    mma8(acc[mf][nf], ah[mf][0], ah[mf][1], ah[mf][2], ah[mf][3],
                         bh[nf][0], bh[nf][1]);
                    mma8(acc[mf][nf], ah[mf][0], ah[mf][1], ah[mf][2], ah[mf][3],
                         bl[nf][0], bl[nf][1]);
                    mma8(acc[mf][nf], al[mf][0], al[mf][1], al[mf][2], al[mf][3],
                         bh[nf][0], bh[nf][1]);
                }
        }

        if (kc + 1 < NCHUNK) {
            STORESTAGE(1 - (kc & 1));       // stores chunk kc+1
            if (kc + 2 < NCHUNK) LOADCHUNK(kc + 2);
        }
        __syncthreads();
    }

    // ---------------- epilogue: bias, square, per-row reduce, atomic ----------------
#pragma unroll
    for (int mf = 0; mf < 4; mf++) {
        float rs0 = 0.f, rs1 = 0.f;
#pragma unroll
        for (int nf = 0; nf < 4; nf++) {
            const int nc = wn * 32 + nf * 8 + 2 * cq;
            float b0 = sbias[nc], b1 = sbias[nc + 1];
            float v;
            v = acc[mf][nf][0] + b0; rs0 += v * v;
            v = acc[mf][nf][1] + b1; rs0 += v * v;
            v = acc[mf][nf][2] + b0; rs1 += v * v;
            v = acc[mf][nf][3] + b1; rs1 += v * v;
        }
        rs0 += __shfl_xor_sync(0xffffffffu, rs0, 1);
        rs0 += __shfl_xor_sync(0xffffffffu, rs0, 2);
        rs1 += __shfl_xor_sync(0xffffffffu, rs1, 1);
        rs1 += __shfl_xor_sync(0xffffffffu, rs1, 2);
        if (cq == 0) {
            const int mrow = row_off + m0 + wm * 64 + mf * 16 + r;
            atomicAdd(&g_sumsq[mrow],     rs0);
            atomicAdd(&g_sumsq[mrow + 8], rs1);
        }
    }
}

// ---------------- finalize ----------------
__global__ void finalize_kernel(const float* __restrict__ phi_scale,
                                const float* __restrict__ phi_bias,
                                float* __restrict__ out)
{
    const int b = blockIdx.x;
    const int tid = threadIdx.x;

    float lw = 0.f, lp = 0.f;
    for (int i = tid; i < 2048; i += 256)
        lw += sqrtf(g_sumsq[b * 2048 + i]);
#pragma unroll
    for (int h = 0; h < 4; h++) {
        int base = ROWS_WHOLE + h * ROWS_WHOLE + b * 2048;
        for (int i = tid; i < 2048; i += 256)
            lp += sqrtf(g_sumsq[base + i]);
    }

    __shared__ float sw[256];
    __shared__ float sp[256];
    sw[tid] = lw; sp[tid] = lp;
    __syncthreads();
    for (int s = 128; s > 0; s >>= 1) {
        if (tid < s) { sw[tid] += sw[tid + s]; sp[tid] += sp[tid + s]; }
        __syncthreads();
    }
    if (tid == 0) {
        float w = sw[0] / 2048.0f;
        float p = sp[0] / 8192.0f;
        float raw = (w - p) / (w + 1e-8f);
        float phi = phi_scale[0] * raw + phi_bias[0];
        out[b] = fminf(fmaxf(phi, 0.0f), 1.0f);
    }
}

extern "C" void kernel_launch(void* const* d_in, const int* in_sizes, int n_in,
                              void* d_out, int out_size)
{
    const float* cur  = (const float*)d_in[0];   // [4,2048,2048]
    const float* hist = (const float*)d_in[1];   // [4,4,2048,2048]
    const float* Ww   = (const float*)d_in[2];   // [1024,2048]
    const float* bw   = (const float*)d_in[3];   // [1024]
    const float* Wp   = (const float*)d_in[4];   // [1024,2048]
    const float* bp   = (const float*)d_in[5];   // [1024]
    const float* ps   = (const float*)d_in[6];
    const float* pb   = (const float*)d_in[7];
    float* out = (float*)d_out;                  // [4]

    cudaFuncSetAttribute(gemm3xtf32_kernel,
                         cudaFuncAttributeMaxDynamicSharedMemorySize, SMEM_BYTES);

    zero_kernel<<<(ROWS_TOTAL + 255) / 256, 256>>>();

    gemm3xtf32_kernel<<<dim3(N_DIM / BN, ROWS_WHOLE / BM), 256, SMEM_BYTES>>>(cur, Ww, bw, 0);
    gemm3xtf32_kernel<<<dim3(N_DIM / BN, ROWS_PARTS / BM), 256, SMEM_BYTES>>>(hist, Wp, bp, ROWS_WHOLE);

    finalize_kernel<<<4, 256>>>(ps, pb, out);
}

// round 5
// speedup vs baseline: 2.0274x; 1.0147x over previous
#include <cuda_runtime.h>
#include <cstdint>

// ---------------- problem constants ----------------
#define K_DIM       2048
#define N_DIM       1024
#define ROWS_WHOLE  8192
#define ROWS_PARTS  32768
#define ROWS_TOTAL  40960

// ---------------- tile config ----------------
#define BM 128
#define BN 128
#define BK 16                      // fp32 elements per K chunk
#define NCHUNK (K_DIM / BK)        // 128
#define SA 20                      // smem row stride in floats (16 + 4 pad, conflict-free)
#define NSTAGE 3

#define A_F      (BM * SA)         // 2560 floats per A tile
#define STAGE_F  (2 * A_F)         // A + B = 5120 floats = 20480 B
#define BIAS_F   (NSTAGE * STAGE_F)
#define SMEM_FLOATS (BIAS_F + BN)
#define SMEM_BYTES  (SMEM_FLOATS * 4)   // 61952 B

__device__ float g_sumsq[ROWS_TOTAL];

// ---------------- helpers ----------------
__device__ __forceinline__ uint32_t smem_u32(const void* p) {
    uint32_t a;
    asm("{ .reg .u64 t; cvta.to.shared.u64 t, %1; cvt.u32.u64 %0, t; }" : "=r"(a) : "l"(p));
    return a;
}
__device__ __forceinline__ uint32_t cvt_tf32(float x) {
    uint32_t r;
    asm("cvt.rna.tf32.f32 %0, %1;" : "=r"(r) : "f"(x));
    return r;
}
__device__ __forceinline__ void cpasync16(uint32_t dst, const void* src) {
    asm volatile("cp.async.ca.shared.global [%0], [%1], 16;" :: "r"(dst), "l"(src) : "memory");
}
__device__ __forceinline__ void cp_commit() {
    asm volatile("cp.async.commit_group;" ::: "memory");
}
__device__ __forceinline__ void cp_wait1() {
    asm volatile("cp.async.wait_group 1;" ::: "memory");
}
__device__ __forceinline__ void cp_wait0() {
    asm volatile("cp.async.wait_group 0;" ::: "memory");
}
__device__ __forceinline__ void mma8(float* c,
                                     uint32_t a0, uint32_t a1, uint32_t a2, uint32_t a3,
                                     uint32_t b0, uint32_t b1) {
    asm volatile(
        "mma.sync.aligned.m16n8k8.row.col.f32.tf32.tf32.f32 "
        "{%0,%1,%2,%3}, {%4,%5,%6,%7}, {%8,%9}, {%0,%1,%2,%3};"
        : "+f"(c[0]), "+f"(c[1]), "+f"(c[2]), "+f"(c[3])
        : "r"(a0), "r"(a1), "r"(a2), "r"(a3), "r"(b0), "r"(b1));
}

__global__ void zero_kernel() {
    int i = blockIdx.x * 256 + threadIdx.x;
    if (i < ROWS_TOTAL) g_sumsq[i] = 0.0f;
}

// ---------------- fused 3xTF32 mma.sync GEMM + row sum-of-squares ----------------
__global__ __launch_bounds__(256, 2)
void gemm3xtf32_kernel(const float* __restrict__ A,
                       const float* __restrict__ W,
                       const float* __restrict__ bias,
                       int row_off)
{
    extern __shared__ __align__(16) float smem[];
    const uint32_t sbase = smem_u32(smem);
    const int tid = threadIdx.x;
    const int wid = tid >> 5;
    const int lid = tid & 31;
    const int wm  = wid >> 2;          // 0..1 : warp row (64 rows)
    const int wn  = wid & 3;           // 0..3 : warp col (32 cols)
    const int r   = lid >> 2;          // 0..7
    const int cq  = lid & 3;           // 0..3
    const int m0  = blockIdx.y * BM;
    const int n0  = blockIdx.x * BN;

    float* sbias = smem + BIAS_F;
    if (tid < BN) sbias[tid] = bias[n0 + tid];

    // global copy coords: thread handles one row-half (8 floats = 2 x 16B)
    const int ar = tid >> 1;           // 0..127
    const int ac = (tid & 1) << 3;     // 0 or 8
    const float* Aptr = A + (size_t)(m0 + ar) * K_DIM + ac;
    const float* Wptr = W + (size_t)(n0 + ar) * K_DIM + ac;
    const uint32_t s_off = (uint32_t)(ar * SA + ac) * 4u;   // bytes within tile

#define ISSUE(kc, s) do { \
        const uint32_t stb_ = sbase + (uint32_t)(s) * (STAGE_F * 4); \
        const float* ag_ = Aptr + (size_t)(kc) * BK; \
        cpasync16(stb_ + s_off,        ag_); \
        cpasync16(stb_ + s_off + 16,   ag_ + 4); \
        const float* wg_ = Wptr + (size_t)(kc) * BK; \
        cpasync16(stb_ + A_F * 4 + s_off,      wg_); \
        cpasync16(stb_ + A_F * 4 + s_off + 16, wg_ + 4); \
        cp_commit(); \
    } while (0)

    float acc[4][4][4];
#pragma unroll
    for (int i = 0; i < 4; i++)
#pragma unroll
        for (int j = 0; j < 4; j++)
#pragma unroll
            for (int q = 0; q < 4; q++) acc[i][j][q] = 0.f;

    ISSUE(0, 0);
    ISSUE(1, 1);

    int s = 0;
    for (int kc = 0; kc < NCHUNK; kc++) {
        if (kc == NCHUNK - 1) cp_wait0(); else cp_wait1();
        __syncthreads();

        if (kc + 2 < NCHUNK) {
            int sn = s + 2; if (sn >= NSTAGE) sn -= NSTAGE;
            ISSUE(kc + 2, sn);
        }

        const float* Ab = smem + s * STAGE_F;
        const float* Bb = Ab + A_F;

#pragma unroll
        for (int ks = 0; ks < 2; ks++) {
            const int k0 = ks * 8 + cq;
            uint32_t ah[4][4], al[4][4];
#pragma unroll
            for (int mf = 0; mf < 4; mf++) {
                const int base = (wm * 64 + mf * 16 + r) * SA + k0;
                float f0 = Ab[base];
                float f1 = Ab[base + 8 * SA];
                float f2 = Ab[base + 4];
                float f3 = Ab[base + 8 * SA + 4];
                ah[mf][0] = cvt_tf32(f0); al[mf][0] = cvt_tf32(f0 - __uint_as_float(ah[mf][0]));
                ah[mf][1] = cvt_tf32(f1); al[mf][1] = cvt_tf32(f1 - __uint_as_float(ah[mf][1]));
                ah[mf][2] = cvt_tf32(f2); al[mf][2] = cvt_tf32(f2 - __uint_as_float(ah[mf][2]));
                ah[mf][3] = cvt_tf32(f3); al[mf][3] = cvt_tf32(f3 - __uint_as_float(ah[mf][3]));
            }
#pragma unroll
            for (int nf = 0; nf < 4; nf++) {
                const int base = (wn * 32 + nf * 8 + r) * SA + k0;
                float b0f = Bb[base];
                float b1f = Bb[base + 4];
                uint32_t bh0 = cvt_tf32(b0f), bh1 = cvt_tf32(b1f);
                uint32_t bl0 = cvt_tf32(b0f - __uint_as_float(bh0));
                uint32_t bl1 = cvt_tf32(b1f - __uint_as_float(bh1));
#pragma unroll
                for (int mf = 0; mf < 4; mf++) {
                    mma8(acc[mf][nf], ah[mf][0], ah[mf][1], ah[mf][2], ah[mf][3], bh0, bh1);
                    mma8(acc[mf][nf], ah[mf][0], ah[mf][1], ah[mf][2], ah[mf][3], bl0, bl1);
                    mma8(acc[mf][nf], al[mf][0], al[mf][1], al[mf][2], al[mf][3], bh0, bh1);
                }
            }
        }

        s++; if (s >= NSTAGE) s = 0;
    }

    // ---------------- epilogue: bias, square, per-row reduce, atomic ----------------
#pragma unroll
    for (int mf = 0; mf < 4; mf++) {
        float rs0 = 0.f, rs1 = 0.f;
#pragma unroll
        for (int nf = 0; nf < 4; nf++) {
            const int nc = wn * 32 + nf * 8 + 2 * cq;
            float b0 = sbias[nc], b1 = sbias[nc + 1];
            float v;
            v = acc[mf][nf][0] + b0; rs0 += v * v;
            v = acc[mf][nf][1] + b1; rs0 += v * v;
            v = acc[mf][nf][2] + b0; rs1 += v * v;
            v = acc[mf][nf][3] + b1; rs1 += v * v;
        }
        rs0 += __shfl_xor_sync(0xffffffffu, rs0, 1);
        rs0 += __shfl_xor_sync(0xffffffffu, rs0, 2);
        rs1 += __shfl_xor_sync(0xffffffffu, rs1, 1);
        rs1 += __shfl_xor_sync(0xffffffffu, rs1, 2);
        if (cq == 0) {
            const int mrow = row_off + m0 + wm * 64 + mf * 16 + r;
            atomicAdd(&g_sumsq[mrow],     rs0);
            atomicAdd(&g_sumsq[mrow + 8], rs1);
        }
    }
}

// ---------------- finalize ----------------
__global__ void finalize_kernel(const float* __restrict__ phi_scale,
                                const float* __restrict__ phi_bias,
                                float* __restrict__ out)
{
    const int b = blockIdx.x;
    const int tid = threadIdx.x;

    float lw = 0.f, lp = 0.f;
    for (int i = tid; i < 2048; i += 256)
        lw += sqrtf(g_sumsq[b * 2048 + i]);
#pragma unroll
    for (int h = 0; h < 4; h++) {
        int base = ROWS_WHOLE + h * ROWS_WHOLE + b * 2048;
        for (int i = tid; i < 2048; i += 256)
            lp += sqrtf(g_sumsq[base + i]);
    }

    __shared__ float sw[256];
    __shared__ float sp[256];
    sw[tid] = lw; sp[tid] = lp;
    __syncthreads();
    for (int s = 128; s > 0; s >>= 1) {
        if (tid < s) { sw[tid] += sw[tid + s]; sp[tid] += sp[tid + s]; }
        __syncthreads();
    }
    if (tid == 0) {
        float w = sw[0] / 2048.0f;
        float p = sp[0] / 8192.0f;
        float raw = (w - p) / (w + 1e-8f);
        float phi = phi_scale[0] * raw + phi_bias[0];
        out[b] = fminf(fmaxf(phi, 0.0f), 1.0f);
    }
}

extern "C" void kernel_launch(void* const* d_in, const int* in_sizes, int n_in,
                              void* d_out, int out_size)
{
    const float* cur  = (const float*)d_in[0];   // [4,2048,2048]
    const float* hist = (const float*)d_in[1];   // [4,4,2048,2048]
    const float* Ww   = (const float*)d_in[2];   // [1024,2048]
    const float* bw   = (const float*)d_in[3];   // [1024]
    const float* Wp   = (const float*)d_in[4];   // [1024,2048]
    const float* bp   = (const float*)d_in[5];   // [1024]
    const float* ps   = (const float*)d_in[6];
    const float* pb   = (const float*)d_in[7];
    float* out = (float*)d_out;                  // [4]

    cudaFuncSetAttribute(gemm3xtf32_kernel,
                         cudaFuncAttributeMaxDynamicSharedMemorySize, SMEM_BYTES);

    zero_kernel<<<(ROWS_TOTAL + 255) / 256, 256>>>();

    gemm3xtf32_kernel<<<dim3(N_DIM / BN, ROWS_WHOLE / BM), 256, SMEM_BYTES>>>(cur, Ww, bw, 0);
    gemm3xtf32_kernel<<<dim3(N_DIM / BN, ROWS_PARTS / BM), 256, SMEM_BYTES>>>(hist, Wp, bp, ROWS_WHOLE);

    finalize_kernel<<<4, 256>>>(ps, pb, out);
}

// round 6
// speedup vs baseline: 3.8336x; 1.8909x over previous
#include <cuda_runtime.h>
#include <cuda_fp16.h>
#include <cstdint>

// ---------------- problem constants ----------------
#define K_DIM       2048
#define N_DIM       1024
#define ROWS_WHOLE  8192
#define ROWS_PARTS  32768
#define ROWS_TOTAL  40960

// ---------------- tile config ----------------
#define BM 128
#define BN 128
#define BK 16                      // k per chunk (one m16n8k16 step)
#define NCHUNK (K_DIM / BK)        // 128
#define SH 24                      // halves per smem row (stride 48B, conflict-free)

#define TERM_H   (BM * SH)         // 3072 halves per term tile
#define AH0_B    0                 // byte offsets of tiles within a stage
#define AH1_B    (TERM_H * 2)
#define BH0_B    (2 * TERM_H * 2)
#define BH1_B    (3 * TERM_H * 2)
#define STAGE_B  (4 * TERM_H * 2)  // 24576 bytes per stage
#define BIAS_B   (2 * STAGE_B)     // bias floats after both stages
#define SMEM_BYTES (BIAS_B + BN * 4)   // 49664

__device__ float g_sumsq[ROWS_TOTAL];

// ---------------- helpers ----------------
__device__ __forceinline__ void mma16(float* c,
                                      uint32_t a0, uint32_t a1, uint32_t a2, uint32_t a3,
                                      uint32_t b0, uint32_t b1) {
    asm volatile(
        "mma.sync.aligned.m16n8k16.row.col.f32.f16.f16.f32 "
        "{%0,%1,%2,%3}, {%4,%5,%6,%7}, {%8,%9}, {%0,%1,%2,%3};"
        : "+f"(c[0]), "+f"(c[1]), "+f"(c[2]), "+f"(c[3])
        : "r"(a0), "r"(a1), "r"(a2), "r"(a3), "r"(b0), "r"(b1));
}

// split 8 consecutive-k floats into packed fp16 h0 (4xb32) and h1 (4xb32)
__device__ __forceinline__ void split8(float4 v0, float4 v1, uint4& H0, uint4& H1) {
    __half2 p0 = __floats2half2_rn(v0.x, v0.y);
    __half2 p1 = __floats2half2_rn(v0.z, v0.w);
    __half2 p2 = __floats2half2_rn(v1.x, v1.y);
    __half2 p3 = __floats2half2_rn(v1.z, v1.w);
    float2 q0 = __half22float2(p0);
    float2 q1 = __half22float2(p1);
    float2 q2 = __half22float2(p2);
    float2 q3 = __half22float2(p3);
    __half2 r0 = __floats2half2_rn(v0.x - q0.x, v0.y - q0.y);
    __half2 r1 = __floats2half2_rn(v0.z - q1.x, v0.w - q1.y);
    __half2 r2 = __floats2half2_rn(v1.x - q2.x, v1.y - q2.y);
    __half2 r3 = __floats2half2_rn(v1.z - q3.x, v1.w - q3.y);
    H0 = make_uint4(*(uint32_t*)&p0, *(uint32_t*)&p1, *(uint32_t*)&p2, *(uint32_t*)&p3);
    H1 = make_uint4(*(uint32_t*)&r0, *(uint32_t*)&r1, *(uint32_t*)&r2, *(uint32_t*)&r3);
}

__global__ void zero_kernel() {
    int i = blockIdx.x * 256 + threadIdx.x;
    if (i < ROWS_TOTAL) g_sumsq[i] = 0.0f;
}

// ---------------- fused fp16x2-split GEMM + row sum-of-squares ----------------
__global__ __launch_bounds__(256, 2)
void gemm_fp16x2_kernel(const float* __restrict__ A,
                        const float* __restrict__ W,
                        const float* __restrict__ bias,
                        int row_off)
{
    extern __shared__ __align__(16) char smem[];
    const int tid = threadIdx.x;
    const int wid = tid >> 5;
    const int lid = tid & 31;
    const int wm  = wid >> 2;          // 0..1 : warp row (64 rows)
    const int wn  = wid & 3;           // 0..3 : warp col (32 cols)
    const int r   = lid >> 2;          // 0..7
    const int cq  = lid & 3;           // 0..3
    const int m0  = blockIdx.y * BM;
    const int n0  = blockIdx.x * BN;

    float* sbias = (float*)(smem + BIAS_B);
    if (tid < BN) sbias[tid] = bias[n0 + tid];

    // global copy coords: thread handles one row-half (8 floats)
    const int ar = tid >> 1;           // 0..127
    const int ac = (tid & 1) << 3;     // 0 or 8
    const float* Aptr = A + (size_t)(m0 + ar) * K_DIM + ac;
    const float* Wptr = W + (size_t)(n0 + ar) * K_DIM + ac;
    const uint32_t s_off = (uint32_t)ar * (SH * 2) + (uint32_t)ac * 2;   // bytes

    float acc[4][4][4];
#pragma unroll
    for (int i = 0; i < 4; i++)
#pragma unroll
        for (int j = 0; j < 4; j++)
#pragma unroll
            for (int q = 0; q < 4; q++) acc[i][j][q] = 0.f;

    float4 av0, av1, bv0, bv1;

#define LOADCHUNK(kc) do { \
        const float* ap_ = Aptr + (size_t)(kc) * BK; \
        av0 = *(const float4*)ap_;  av1 = *(const float4*)(ap_ + 4); \
        const float* wp_ = Wptr + (size_t)(kc) * BK; \
        bv0 = *(const float4*)wp_;  bv1 = *(const float4*)(wp_ + 4); \
    } while (0)

#define STORESTAGE(s) do { \
        char* st_ = smem + (s) * STAGE_B; \
        uint4 H0_, H1_; \
        split8(av0, av1, H0_, H1_); \
        *(uint4*)(st_ + AH0_B + s_off) = H0_; \
        *(uint4*)(st_ + AH1_B + s_off) = H1_; \
        split8(bv0, bv1, H0_, H1_); \
        *(uint4*)(st_ + BH0_B + s_off) = H0_; \
        *(uint4*)(st_ + BH1_B + s_off) = H1_; \
    } while (0)

    LOADCHUNK(0);
    STORESTAGE(0);
    LOADCHUNK(1);
    __syncthreads();

    for (int kc = 0; kc < NCHUNK; kc++) {
        const char* st = smem + (kc & 1) * STAGE_B;

        // B fragments: h0 and h1 for 4 n-blocks
        uint32_t b0h[4], b1h[4], b0l[4], b1l[4];
#pragma unroll
        for (int nf = 0; nf < 4; nf++) {
            const int off = ((wn * 32 + nf * 8 + r) * SH + 2 * cq) * 2;
            b0h[nf] = *(const uint32_t*)(st + BH0_B + off);
            b1h[nf] = *(const uint32_t*)(st + BH0_B + off + 16);
            b0l[nf] = *(const uint32_t*)(st + BH1_B + off);
            b1l[nf] = *(const uint32_t*)(st + BH1_B + off + 16);
        }

#pragma unroll
        for (int mf = 0; mf < 4; mf++) {
            const int off0 = ((wm * 64 + mf * 16 + r) * SH + 2 * cq) * 2;
            const int off1 = off0 + 8 * SH * 2;
            uint32_t ah0 = *(const uint32_t*)(st + AH0_B + off0);
            uint32_t ah1 = *(const uint32_t*)(st + AH0_B + off1);
            uint32_t ah2 = *(const uint32_t*)(st + AH0_B + off0 + 16);
            uint32_t ah3 = *(const uint32_t*)(st + AH0_B + off1 + 16);
            uint32_t al0 = *(const uint32_t*)(st + AH1_B + off0);
            uint32_t al1 = *(const uint32_t*)(st + AH1_B + off1);
            uint32_t al2 = *(const uint32_t*)(st + AH1_B + off0 + 16);
            uint32_t al3 = *(const uint32_t*)(st + AH1_B + off1 + 16);
#pragma unroll
            for (int nf = 0; nf < 4; nf++) {
                mma16(acc[mf][nf], ah0, ah1, ah2, ah3, b0h[nf], b1h[nf]);  // h0*h0
                mma16(acc[mf][nf], ah0, ah1, ah2, ah3, b0l[nf], b1l[nf]);  // h0*h1
                mma16(acc[mf][nf], al0, al1, al2, al3, b0h[nf], b1h[nf]);  // h1*h0
            }
        }

        if (kc + 1 < NCHUNK) {
            STORESTAGE((kc + 1) & 1);
            if (kc + 2 < NCHUNK) LOADCHUNK(kc + 2);
        }
        __syncthreads();
    }

    // ---------------- epilogue: bias, square, per-row reduce, atomic ----------------
#pragma unroll
    for (int mf = 0; mf < 4; mf++) {
        float rs0 = 0.f, rs1 = 0.f;
#pragma unroll
        for (int nf = 0; nf < 4; nf++) {
            const int nc = wn * 32 + nf * 8 + 2 * cq;
            float b0 = sbias[nc], b1 = sbias[nc + 1];
            float v;
            v = acc[mf][nf][0] + b0; rs0 += v * v;
            v = acc[mf][nf][1] + b1; rs0 += v * v;
            v = acc[mf][nf][2] + b0; rs1 += v * v;
            v = acc[mf][nf][3] + b1; rs1 += v * v;
        }
        rs0 += __shfl_xor_sync(0xffffffffu, rs0, 1);
        rs0 += __shfl_xor_sync(0xffffffffu, rs0, 2);
        rs1 += __shfl_xor_sync(0xffffffffu, rs1, 1);
        rs1 += __shfl_xor_sync(0xffffffffu, rs1, 2);
        if (cq == 0) {
            const int mrow = row_off + m0 + wm * 64 + mf * 16 + r;
            atomicAdd(&g_sumsq[mrow],     rs0);
            atomicAdd(&g_sumsq[mrow + 8], rs1);
        }
    }
}

// ---------------- finalize ----------------
__global__ void finalize_kernel(const float* __restrict__ phi_scale,
                                const float* __restrict__ phi_bias,
                                float* __restrict__ out)
{
    const int b = blockIdx.x;
    const int tid = threadIdx.x;

    float lw = 0.f, lp = 0.f;
    for (int i = tid; i < 2048; i += 256)
        lw += sqrtf(g_sumsq[b * 2048 + i]);
#pragma unroll
    for (int h = 0; h < 4; h++) {
        int base = ROWS_WHOLE + h * ROWS_WHOLE + b * 2048;
        for (int i = tid; i < 2048; i += 256)
            lp += sqrtf(g_sumsq[base + i]);
    }

    __shared__ float sw[256];
    __shared__ float sp[256];
    sw[tid] = lw; sp[tid] = lp;
    __syncthreads();
    for (int s = 128; s > 0; s >>= 1) {
        if (tid < s) { sw[tid] += sw[tid + s]; sp[tid] += sp[tid + s]; }
        __syncthreads();
    }
    if (tid == 0) {
        float w = sw[0] / 2048.0f;
        float p = sp[0] / 8192.0f;
        float raw = (w - p) / (w + 1e-8f);
        float phi = phi_scale[0] * raw + phi_bias[0];
        out[b] = fminf(fmaxf(phi, 0.0f), 1.0f);
    }
}

extern "C" void kernel_launch(void* const* d_in, const int* in_sizes, int n_in,
                              void* d_out, int out_size)
{
    const float* cur  = (const float*)d_in[0];   // [4,2048,2048]
    const float* hist = (const float*)d_in[1];   // [4,4,2048,2048]
    const float* Ww   = (const float*)d_in[2];   // [1024,2048]
    const float* bw   = (const float*)d_in[3];   // [1024]
    const float* Wp   = (const float*)d_in[4];   // [1024,2048]
    const float* bp   = (const float*)d_in[5];   // [1024]
    const float* ps   = (const float*)d_in[6];
    const float* pb   = (const float*)d_in[7];
    float* out = (float*)d_out;                  // [4]

    cudaFuncSetAttribute(gemm_fp16x2_kernel,
                         cudaFuncAttributeMaxDynamicSharedMemorySize, SMEM_BYTES);

    zero_kernel<<<(ROWS_TOTAL + 255) / 256, 256>>>();

    gemm_fp16x2_kernel<<<dim3(N_DIM / BN, ROWS_WHOLE / BM), 256, SMEM_BYTES>>>(cur, Ww, bw, 0);
    gemm_fp16x2_kernel<<<dim3(N_DIM / BN, ROWS_PARTS / BM), 256, SMEM_BYTES>>>(hist, Wp, bp, ROWS_WHOLE);

    finalize_kernel<<<4, 256>>>(ps, pb, out);
}